// round 2
// baseline (speedup 1.0000x reference)
#include <cuda_runtime.h>
#include <cstdint>

#define MAX_N 50000
#define MAX_E 800000
#define IN_C  256
#define HID   128
#define OUTC  64

// ---- scratch (device globals: no allocations allowed) ----
__device__ int   g_is64;
__device__ int   g_src[MAX_E];
__device__ int   g_dst[MAX_E];
__device__ float g_deg[MAX_N];
__device__ float g_dis[MAX_N];
__device__ float g_hs1[MAX_N * HID];   // dis-scaled layer-1 GEMM output, later reused as relu'd activation
__device__ float g_agg1[MAX_N * HID];  // layer-1 aggregation buffer
__device__ float g_hs2[MAX_N * OUTC];  // dis-scaled layer-2 GEMM output

__device__ __forceinline__ void red_add_v4(float* p, float4 v) {
    asm volatile("red.global.add.v4.f32 [%0], {%1,%2,%3,%4};"
                 :: "l"(p), "f"(v.x), "f"(v.y), "f"(v.z), "f"(v.w) : "memory");
}

// ---------------- edge index dtype detection + conversion ----------------
// If the buffer is really int64, the first 256 values (read as int64) are all
// in [0, MAX_N). If it is int32, a 64-bit read combines two random indices:
// value >= 2^32 unless the high half is 0 (prob ~ (1/50000)^k). Deterministic.
__global__ void k_detect(const long long* __restrict__ ei) {
    __shared__ int ok;
    if (threadIdx.x == 0) ok = 1;
    __syncthreads();
    long long v = ei[threadIdx.x];
    if (v < 0 || v >= MAX_N) ok = 0;
    __syncthreads();
    if (threadIdx.x == 0) g_is64 = ok;
}

__global__ void k_convert(const void* __restrict__ ei, int E) {
    int i = blockIdx.x * blockDim.x + threadIdx.x;
    if (i >= E) return;
    if (g_is64) {
        const long long* p = (const long long*)ei;
        g_src[i] = (int)p[i];
        g_dst[i] = (int)p[i + E];
    } else {
        const int* p = (const int*)ei;
        g_src[i] = p[i];
        g_dst[i] = p[i + E];
    }
}

// ---------------- degree / normalization ----------------
__global__ void k_deg_init(int n) {
    int i = blockIdx.x * blockDim.x + threadIdx.x;
    if (i < n) g_deg[i] = 1.0f;  // self loop
}

__global__ void k_deg_count(int E) {
    int i = blockIdx.x * blockDim.x + threadIdx.x;
    if (i < E) atomicAdd(&g_deg[g_dst[i]], 1.0f);
}

__global__ void k_dis(int n) {
    int i = blockIdx.x * blockDim.x + threadIdx.x;
    if (i < n) g_dis[i] = rsqrtf(g_deg[i]);
}

// ---------------- tiled SGEMM with dis-scaled epilogue ----------------
// Computes v = dis[row] * (A[row,:] @ W[:,col]) and stores v to BOTH out1 and out2.
// BN == full output width (N dim fully covered per block).
template<int BM, int BN, int BK, int TM, int TN>
__global__ void __launch_bounds__((BM/TM)*(BN/TN))
sgemm_dis(const float* __restrict__ A, const float* __restrict__ W,
          float* __restrict__ out1, float* __restrict__ out2,
          int M, int K)
{
    constexpr int TX = BN / TN;
    constexpr int TY = BM / TM;
    constexpr int NT = TX * TY;

    __shared__ float As[BM][BK + 4];
    __shared__ float Bs[BK][BN + 4];

    const int tid = threadIdx.x;
    const int tx = tid % TX;
    const int ty = tid / TX;
    const int row0 = blockIdx.x * BM;

    float acc[TM][TN];
#pragma unroll
    for (int i = 0; i < TM; i++)
#pragma unroll
        for (int j = 0; j < TN; j++) acc[i][j] = 0.0f;

    for (int kk = 0; kk < K; kk += BK) {
        // load A tile (coalesced along K)
        for (int idx = tid; idx < BM * BK; idx += NT) {
            int r = idx / BK, c = idx % BK;
            int gr = row0 + r;
            As[r][c] = (gr < M) ? A[(size_t)gr * K + kk + c] : 0.0f;
        }
        // load W tile (coalesced along N)
        for (int idx = tid; idx < BK * BN; idx += NT) {
            int r = idx / BN, c = idx % BN;
            Bs[r][c] = W[(size_t)(kk + r) * BN + c];
        }
        __syncthreads();

#pragma unroll
        for (int k = 0; k < BK; k++) {
            float ra[TM], rb[TN];
#pragma unroll
            for (int i = 0; i < TM; i++) ra[i] = As[ty * TM + i][k];
#pragma unroll
            for (int j = 0; j < TN; j++) rb[j] = Bs[k][tx * TN + j];
#pragma unroll
            for (int i = 0; i < TM; i++)
#pragma unroll
                for (int j = 0; j < TN; j++)
                    acc[i][j] = fmaf(ra[i], rb[j], acc[i][j]);
        }
        __syncthreads();
    }

#pragma unroll
    for (int i = 0; i < TM; i++) {
        int gr = row0 + ty * TM + i;
        if (gr >= M) continue;
        float d = g_dis[gr];
#pragma unroll
        for (int j = 0; j < TN; j++) {
            size_t o = (size_t)gr * BN + tx * TN + j;
            float v = acc[i][j] * d;
            out1[o] = v;
            out2[o] = v;
        }
    }
}

// ---------------- edge scatter: agg[dst] += hs[src] ----------------
template<int F>
__global__ void k_scatter(const float* __restrict__ hs,
                          float* __restrict__ agg, int E)
{
    constexpr int LPE = F / 4;  // float4 lanes per edge
    long long gid = (long long)blockIdx.x * blockDim.x + threadIdx.x;
    int e = (int)(gid / LPE);
    if (e >= E) return;
    int lane = (int)(gid % LPE);
    int s = g_src[e];
    int d = g_dst[e];
    float4 v = reinterpret_cast<const float4*>(hs + (size_t)s * F)[lane];
    red_add_v4(agg + (size_t)d * F + lane * 4, v);
}

// ---------------- epilogues ----------------
__global__ void k_fin1(const float* __restrict__ b1, int n) {
    int i = blockIdx.x * blockDim.x + threadIdx.x;
    if (i >= n * HID) return;
    int v = i / HID, c = i % HID;
    float val = g_dis[v] * g_agg1[i] + b1[c];
    g_hs1[i] = fmaxf(val, 0.0f);   // reuse hs1 buffer as relu'd activation
}

__global__ void k_fin2(float* __restrict__ out, const float* __restrict__ b2, int n) {
    int i = blockIdx.x * blockDim.x + threadIdx.x;
    if (i >= n * OUTC) return;
    int v = i / OUTC, c = i % OUTC;
    out[i] = g_dis[v] * out[i] + b2[c];
}

// ---------------- launch ----------------
extern "C" void kernel_launch(void* const* d_in, const int* in_sizes, int n_in,
                              void* d_out, int out_size)
{
    const float* x   = (const float*)d_in[0];
    const void*  ei  = d_in[1];
    const float* W1  = (const float*)d_in[2];
    const float* b1  = (const float*)d_in[3];
    const float* W2  = (const float*)d_in[4];
    const float* b2  = (const float*)d_in[5];
    float*       out = (float*)d_out;

    const int N = in_sizes[0] / IN_C;   // 50000
    const int E = in_sizes[1] / 2;      // 800000

    float *p_hs1, *p_agg1, *p_hs2;
    cudaGetSymbolAddress((void**)&p_hs1,  g_hs1);
    cudaGetSymbolAddress((void**)&p_agg1, g_agg1);
    cudaGetSymbolAddress((void**)&p_hs2,  g_hs2);

    // 0) detect index dtype, normalize to int32
    k_detect<<<1, 256>>>((const long long*)ei);
    k_convert<<<(E + 255) / 256, 256>>>(ei, E);

    // 1) degrees + inverse-sqrt
    k_deg_init<<<(N + 255) / 256, 256>>>(N);
    k_deg_count<<<(E + 255) / 256, 256>>>(E);
    k_dis<<<(N + 255) / 256, 256>>>(N);

    // 2) layer 1 GEMM: hs1 = dis * (x @ W1); also seed agg1 with self-loop term
    {
        constexpr int BM = 64, BN = HID, BK = 32, TM = 8, TN = 8;
        sgemm_dis<BM, BN, BK, TM, TN>
            <<<(N + BM - 1) / BM, (BM / TM) * (BN / TN)>>>(x, W1, p_hs1, p_agg1, N, IN_C);
    }

    // 3) layer 1 edge scatter
    {
        long long total = (long long)E * (HID / 4);
        k_scatter<HID><<<(unsigned)((total + 255) / 256), 256>>>(p_hs1, p_agg1, E);
    }

    // 4) layer 1 epilogue: relu(dis*agg1 + b1) -> act1 (reuses hs1)
    k_fin1<<<(N * HID + 255) / 256, 256>>>(b1, N);

    // 5) layer 2 GEMM: hs2 = dis * (act1 @ W2); seed d_out with self-loop term
    {
        constexpr int BM = 128, BN = OUTC, BK = 32, TM = 8, TN = 4;
        sgemm_dis<BM, BN, BK, TM, TN>
            <<<(N + BM - 1) / BM, (BM / TM) * (BN / TN)>>>(p_hs1, W2, p_hs2, out, N, HID);
    }

    // 6) layer 2 edge scatter (directly into d_out)
    {
        long long total = (long long)E * (OUTC / 4);
        k_scatter<OUTC><<<(unsigned)((total + 255) / 256), 256>>>(p_hs2, out, E);
    }

    // 7) final epilogue: out = dis*out + b2
    k_fin2<<<(N * OUTC + 255) / 256, 256>>>(out, b2, N);
}

// round 3
// speedup vs baseline: 1.4198x; 1.4198x over previous
#include <cuda_runtime.h>
#include <cstdint>

#define MAX_N 50000
#define MAX_E 800000
#define IN_C  256
#define HID   128
#define OUTC  64
#define SCAN_B 256
#define SCAN_NBLK ((MAX_N + SCAN_B - 1) / SCAN_B)   // 196

// ---- scratch (device globals: no allocations allowed) ----
__device__ int   g_is64;
__device__ int   g_src[MAX_E];
__device__ int   g_dst[MAX_E];
__device__ int   g_csr[MAX_E];         // src indices grouped by dst
__device__ int   g_cnt[MAX_N];         // in-degree (excl self loop)
__device__ int   g_start[MAX_N];       // CSR row start (exclusive prefix of cnt)
__device__ int   g_cursor[MAX_N];
__device__ int   g_bsum[SCAN_NBLK];
__device__ int   g_boff[SCAN_NBLK];
__device__ float g_dis[MAX_N];
__device__ float g_hs1[MAX_N * HID];   // dis-scaled layer-1 GEMM output
__device__ float g_act1[MAX_N * HID];  // relu'd layer-1 output
__device__ float g_hs2[MAX_N * OUTC];  // dis-scaled layer-2 GEMM output

// ---------------- edge index dtype detection + conversion ----------------
__global__ void k_detect(const long long* __restrict__ ei) {
    __shared__ int ok;
    if (threadIdx.x == 0) ok = 1;
    __syncthreads();
    long long v = ei[threadIdx.x];
    if (v < 0 || v >= MAX_N) ok = 0;
    __syncthreads();
    if (threadIdx.x == 0) g_is64 = ok;
}

__global__ void k_convert(const void* __restrict__ ei, int E) {
    int i = blockIdx.x * blockDim.x + threadIdx.x;
    if (i >= E) return;
    if (g_is64) {
        const long long* p = (const long long*)ei;
        g_src[i] = (int)p[i];
        g_dst[i] = (int)p[i + E];
    } else {
        const int* p = (const int*)ei;
        g_src[i] = p[i];
        g_dst[i] = p[i + E];
    }
}

// ---------------- CSR build ----------------
__global__ void k_zero_cnt(int n) {
    int i = blockIdx.x * blockDim.x + threadIdx.x;
    if (i < n) g_cnt[i] = 0;
}

__global__ void k_hist(int E) {
    int i = blockIdx.x * blockDim.x + threadIdx.x;
    if (i < E) atomicAdd(&g_cnt[g_dst[i]], 1);
}

// block-wise inclusive scan; writes per-element exclusive, per-block total
__global__ void k_scan1(int n) {
    __shared__ int s[SCAN_B];
    int i = blockIdx.x * SCAN_B + threadIdx.x;
    int v = (i < n) ? g_cnt[i] : 0;
    s[threadIdx.x] = v;
    __syncthreads();
#pragma unroll
    for (int off = 1; off < SCAN_B; off <<= 1) {
        int x = (threadIdx.x >= off) ? s[threadIdx.x - off] : 0;
        __syncthreads();
        s[threadIdx.x] += x;
        __syncthreads();
    }
    if (i < n) g_start[i] = s[threadIdx.x] - v;   // exclusive within block
    if (threadIdx.x == SCAN_B - 1) g_bsum[blockIdx.x] = s[SCAN_B - 1];
}

__global__ void k_scan2(int nblk) {
    __shared__ int s[SCAN_B];
    int v = (threadIdx.x < nblk) ? g_bsum[threadIdx.x] : 0;
    s[threadIdx.x] = v;
    __syncthreads();
#pragma unroll
    for (int off = 1; off < SCAN_B; off <<= 1) {
        int x = (threadIdx.x >= off) ? s[threadIdx.x - off] : 0;
        __syncthreads();
        s[threadIdx.x] += x;
        __syncthreads();
    }
    if (threadIdx.x < nblk) g_boff[threadIdx.x] = s[threadIdx.x] - v;  // exclusive
}

__global__ void k_scan3(int n) {
    int i = blockIdx.x * blockDim.x + threadIdx.x;
    if (i >= n) return;
    int st = g_start[i] + g_boff[i >> 8];
    g_start[i]  = st;
    g_cursor[i] = st;
    g_dis[i]    = rsqrtf((float)(g_cnt[i] + 1));   // +1 self loop
}

__global__ void k_fill(int E) {
    int i = blockIdx.x * blockDim.x + threadIdx.x;
    if (i >= E) return;
    int pos = atomicAdd(&g_cursor[g_dst[i]], 1);
    g_csr[pos] = g_src[i];
}

// ---------------- tiled SGEMM with dis-scaled epilogue ----------------
template<int BM, int BN, int BK, int TM, int TN>
__global__ void __launch_bounds__((BM/TM)*(BN/TN))
sgemm_dis(const float* __restrict__ A, const float* __restrict__ W,
          float* __restrict__ out, int M, int K)
{
    constexpr int TX = BN / TN;
    constexpr int TY = BM / TM;
    constexpr int NT = TX * TY;

    __shared__ float As[BM][BK + 4];
    __shared__ float Bs[BK][BN + 4];

    const int tid = threadIdx.x;
    const int tx = tid % TX;
    const int ty = tid / TX;
    const int row0 = blockIdx.x * BM;

    float acc[TM][TN];
#pragma unroll
    for (int i = 0; i < TM; i++)
#pragma unroll
        for (int j = 0; j < TN; j++) acc[i][j] = 0.0f;

    for (int kk = 0; kk < K; kk += BK) {
        for (int idx = tid; idx < BM * BK; idx += NT) {
            int r = idx / BK, c = idx % BK;
            int gr = row0 + r;
            As[r][c] = (gr < M) ? A[(size_t)gr * K + kk + c] : 0.0f;
        }
        for (int idx = tid; idx < BK * BN; idx += NT) {
            int r = idx / BN, c = idx % BN;
            Bs[r][c] = W[(size_t)(kk + r) * BN + c];
        }
        __syncthreads();

#pragma unroll
        for (int k = 0; k < BK; k++) {
            float ra[TM], rb[TN];
#pragma unroll
            for (int i = 0; i < TM; i++) ra[i] = As[ty * TM + i][k];
#pragma unroll
            for (int j = 0; j < TN; j++) rb[j] = Bs[k][tx * TN + j];
#pragma unroll
            for (int i = 0; i < TM; i++)
#pragma unroll
                for (int j = 0; j < TN; j++)
                    acc[i][j] = fmaf(ra[i], rb[j], acc[i][j]);
        }
        __syncthreads();
    }

#pragma unroll
    for (int i = 0; i < TM; i++) {
        int gr = row0 + ty * TM + i;
        if (gr >= M) continue;
        float d = g_dis[gr];
#pragma unroll
        for (int j = 0; j < TN; j++)
            out[(size_t)gr * BN + tx * TN + j] = acc[i][j] * d;
    }
}

// ---------------- gather aggregation, fused epilogue ----------------
// F=128: one warp per node, lane handles float4 (32*4 = 128).
__global__ void k_agg128(const float* __restrict__ hs, float* __restrict__ out,
                         const float* __restrict__ bias, int N)
{
    int w = (blockIdx.x * blockDim.x + threadIdx.x) >> 5;
    if (w >= N) return;
    int lane = threadIdx.x & 31;
    const float4* base = (const float4*)hs;

    int beg = g_start[w], cnt = g_cnt[w];
    float4 a0 = base[(size_t)w * 32 + lane];   // self loop term
    float4 a1 = make_float4(0.f, 0.f, 0.f, 0.f);
    int e = 0;
    for (; e + 4 <= cnt; e += 4) {
        int s0 = g_csr[beg + e], s1 = g_csr[beg + e + 1];
        int s2 = g_csr[beg + e + 2], s3 = g_csr[beg + e + 3];
        float4 v0 = base[(size_t)s0 * 32 + lane];
        float4 v1 = base[(size_t)s1 * 32 + lane];
        float4 v2 = base[(size_t)s2 * 32 + lane];
        float4 v3 = base[(size_t)s3 * 32 + lane];
        a0.x += v0.x + v1.x; a0.y += v0.y + v1.y; a0.z += v0.z + v1.z; a0.w += v0.w + v1.w;
        a1.x += v2.x + v3.x; a1.y += v2.y + v3.y; a1.z += v2.z + v3.z; a1.w += v2.w + v3.w;
    }
    for (; e < cnt; e++) {
        int s = g_csr[beg + e];
        float4 v = base[(size_t)s * 32 + lane];
        a0.x += v.x; a0.y += v.y; a0.z += v.z; a0.w += v.w;
    }
    float d = g_dis[w];
    float4 b = ((const float4*)bias)[lane];
    float4 r;
    r.x = fmaxf(fmaf(d, a0.x + a1.x, b.x), 0.f);
    r.y = fmaxf(fmaf(d, a0.y + a1.y, b.y), 0.f);
    r.z = fmaxf(fmaf(d, a0.z + a1.z, b.z), 0.f);
    r.w = fmaxf(fmaf(d, a0.w + a1.w, b.w), 0.f);
    ((float4*)out)[(size_t)w * 32 + lane] = r;
}

// F=64: half-warp per node, lane handles float4 (16*4 = 64). No relu, writes d_out.
__global__ void k_agg64(const float* __restrict__ hs, float* __restrict__ out,
                        const float* __restrict__ bias, int N)
{
    int t = blockIdx.x * blockDim.x + threadIdx.x;
    int node = t >> 4;
    if (node >= N) return;
    int l = t & 15;
    const float4* base = (const float4*)hs;

    int beg = g_start[node], cnt = g_cnt[node];
    float4 a0 = base[(size_t)node * 16 + l];   // self loop
    float4 a1 = make_float4(0.f, 0.f, 0.f, 0.f);
    int e = 0;
    for (; e + 4 <= cnt; e += 4) {
        int s0 = g_csr[beg + e], s1 = g_csr[beg + e + 1];
        int s2 = g_csr[beg + e + 2], s3 = g_csr[beg + e + 3];
        float4 v0 = base[(size_t)s0 * 16 + l];
        float4 v1 = base[(size_t)s1 * 16 + l];
        float4 v2 = base[(size_t)s2 * 16 + l];
        float4 v3 = base[(size_t)s3 * 16 + l];
        a0.x += v0.x + v1.x; a0.y += v0.y + v1.y; a0.z += v0.z + v1.z; a0.w += v0.w + v1.w;
        a1.x += v2.x + v3.x; a1.y += v2.y + v3.y; a1.z += v2.z + v3.z; a1.w += v2.w + v3.w;
    }
    for (; e < cnt; e++) {
        int s = g_csr[beg + e];
        float4 v = base[(size_t)s * 16 + l];
        a0.x += v.x; a0.y += v.y; a0.z += v.z; a0.w += v.w;
    }
    float d = g_dis[node];
    float4 b = ((const float4*)bias)[l];
    float4 r;
    r.x = fmaf(d, a0.x + a1.x, b.x);
    r.y = fmaf(d, a0.y + a1.y, b.y);
    r.z = fmaf(d, a0.z + a1.z, b.z);
    r.w = fmaf(d, a0.w + a1.w, b.w);
    ((float4*)out)[(size_t)node * 16 + l] = r;
}

// ---------------- launch ----------------
extern "C" void kernel_launch(void* const* d_in, const int* in_sizes, int n_in,
                              void* d_out, int out_size)
{
    const float* x   = (const float*)d_in[0];
    const void*  ei  = d_in[1];
    const float* W1  = (const float*)d_in[2];
    const float* b1  = (const float*)d_in[3];
    const float* W2  = (const float*)d_in[4];
    const float* b2  = (const float*)d_in[5];
    float*       out = (float*)d_out;

    const int N = in_sizes[0] / IN_C;   // 50000
    const int E = in_sizes[1] / 2;      // 800000
    const int nscan = (N + SCAN_B - 1) / SCAN_B;

    float *p_hs1, *p_act1, *p_hs2;
    cudaGetSymbolAddress((void**)&p_hs1,  g_hs1);
    cudaGetSymbolAddress((void**)&p_act1, g_act1);
    cudaGetSymbolAddress((void**)&p_hs2,  g_hs2);

    // 0) normalize edge index to int32
    k_detect<<<1, 256>>>((const long long*)ei);
    k_convert<<<(E + 255) / 256, 256>>>(ei, E);

    // 1) CSR build + dis
    k_zero_cnt<<<(N + 255) / 256, 256>>>(N);
    k_hist<<<(E + 255) / 256, 256>>>(E);
    k_scan1<<<nscan, SCAN_B>>>(N);
    k_scan2<<<1, SCAN_B>>>(nscan);
    k_scan3<<<(N + 255) / 256, 256>>>(N);
    k_fill<<<(E + 255) / 256, 256>>>(E);

    // 2) layer 1 GEMM: hs1 = dis * (x @ W1)
    {
        constexpr int BM = 128, BN = HID, BK = 32, TM = 8, TN = 8;
        sgemm_dis<BM, BN, BK, TM, TN>
            <<<(N + BM - 1) / BM, (BM / TM) * (BN / TN)>>>(x, W1, p_hs1, N, IN_C);
    }

    // 3) layer 1 gather-aggregate + relu + bias
    k_agg128<<<(N * 32 + 255) / 256, 256>>>(p_hs1, p_act1, b1, N);

    // 4) layer 2 GEMM: hs2 = dis * (act1 @ W2)
    {
        constexpr int BM = 128, BN = OUTC, BK = 32, TM = 8, TN = 4;
        sgemm_dis<BM, BN, BK, TM, TN>
            <<<(N + BM - 1) / BM, (BM / TM) * (BN / TN)>>>(p_act1, W2, p_hs2, N, HID);
    }

    // 5) layer 2 gather-aggregate + bias -> d_out
    k_agg64<<<(N * 16 + 255) / 256, 256>>>(p_hs2, out, b2, N);
}

// round 4
// speedup vs baseline: 1.9161x; 1.3496x over previous
#include <cuda_runtime.h>
#include <cstdint>

#define MAX_N 50000
#define MAX_E 800000
#define IN_C  256
#define HID   128
#define OUTC  64
#define SCAN_B 256
#define SCAN_NBLK ((MAX_N + SCAN_B - 1) / SCAN_B)   // 196

// ---- scratch (device globals: no allocations allowed) ----
__device__ int   g_is64;
__device__ int   g_src[MAX_E];
__device__ int   g_dst[MAX_E];
__device__ int   g_csr[MAX_E];         // src indices grouped by dst
__device__ int   g_cnt[MAX_N];         // in-degree (excl self loop)
__device__ int   g_start[MAX_N];       // CSR row start
__device__ int   g_cursor[MAX_N];
__device__ int   g_bsum[SCAN_NBLK];
__device__ int   g_boff[SCAN_NBLK];
__device__ float g_dis[MAX_N];
__device__ float g_hs1[MAX_N * HID];
__device__ float g_act1[MAX_N * HID];
__device__ float g_hs2[MAX_N * OUTC];

// ---------------- edge index dtype detection + conversion+hist ----------------
__global__ void k_detect(const long long* __restrict__ ei) {
    __shared__ int ok;
    if (threadIdx.x == 0) ok = 1;
    __syncthreads();
    long long v = ei[threadIdx.x];
    if (v < 0 || v >= MAX_N) ok = 0;
    __syncthreads();
    if (threadIdx.x == 0) g_is64 = ok;
}

__global__ void k_zero_cnt(int n) {
    int i = blockIdx.x * blockDim.x + threadIdx.x;
    if (i < n) g_cnt[i] = 0;
}

// one pass: normalize to int32 AND build the dst histogram
__global__ void k_convert_hist(const void* __restrict__ ei, int E) {
    int i = blockIdx.x * blockDim.x + threadIdx.x;
    if (i >= E) return;
    int s, d;
    if (g_is64) {
        const long long* p = (const long long*)ei;
        s = (int)p[i]; d = (int)p[i + E];
    } else {
        const int* p = (const int*)ei;
        s = p[i]; d = p[i + E];
    }
    g_src[i] = s;
    g_dst[i] = d;
    atomicAdd(&g_cnt[d], 1);
}

// ---------------- scans ----------------
__global__ void k_scan1(int n) {
    __shared__ int s[SCAN_B];
    int i = blockIdx.x * SCAN_B + threadIdx.x;
    int v = (i < n) ? g_cnt[i] : 0;
    s[threadIdx.x] = v;
    __syncthreads();
#pragma unroll
    for (int off = 1; off < SCAN_B; off <<= 1) {
        int x = (threadIdx.x >= off) ? s[threadIdx.x - off] : 0;
        __syncthreads();
        s[threadIdx.x] += x;
        __syncthreads();
    }
    if (i < n) g_start[i] = s[threadIdx.x] - v;
    if (threadIdx.x == SCAN_B - 1) g_bsum[blockIdx.x] = s[SCAN_B - 1];
}

__global__ void k_scan2(int nblk) {
    __shared__ int s[SCAN_B];
    int v = (threadIdx.x < nblk) ? g_bsum[threadIdx.x] : 0;
    s[threadIdx.x] = v;
    __syncthreads();
#pragma unroll
    for (int off = 1; off < SCAN_B; off <<= 1) {
        int x = (threadIdx.x >= off) ? s[threadIdx.x - off] : 0;
        __syncthreads();
        s[threadIdx.x] += x;
        __syncthreads();
    }
    if (threadIdx.x < nblk) g_boff[threadIdx.x] = s[threadIdx.x] - v;
}

__global__ void k_scan3(int n) {
    int i = blockIdx.x * blockDim.x + threadIdx.x;
    if (i >= n) return;
    int st = g_start[i] + g_boff[i >> 8];
    g_start[i]  = st;
    g_cursor[i] = st;
    g_dis[i]    = rsqrtf((float)(g_cnt[i] + 1));   // +1 self loop
}

__global__ void k_fill(int E) {
    int i = blockIdx.x * blockDim.x + threadIdx.x;
    if (i >= E) return;
    int pos = atomicAdd(&g_cursor[g_dst[i]], 1);
    g_csr[pos] = g_src[i];
}

// ---------------- split-tf32 tensor-core GEMM, dis-scaled epilogue ----------------
__device__ __forceinline__ void cvt_split(float x, unsigned& hi, unsigned& lo) {
    asm("cvt.rna.tf32.f32 %0, %1;" : "=r"(hi) : "f"(x));
    float l = x - __uint_as_float(hi);
    asm("cvt.rna.tf32.f32 %0, %1;" : "=r"(lo) : "f"(l));
}

__device__ __forceinline__ void mma8(float* c, const unsigned* a, const unsigned* b) {
    asm volatile(
        "mma.sync.aligned.m16n8k8.row.col.f32.tf32.tf32.f32 "
        "{%0,%1,%2,%3},{%4,%5,%6,%7},{%8,%9},{%0,%1,%2,%3};"
        : "+f"(c[0]), "+f"(c[1]), "+f"(c[2]), "+f"(c[3])
        : "r"(a[0]), "r"(a[1]), "r"(a[2]), "r"(a[3]), "r"(b[0]), "r"(b[1]));
}

// out[row] = dis[row] * (A[row,:] @ W[:,col]) ; A:[M,K] row-major, W:[K,BN] row-major
template<int BN>
__global__ void __launch_bounds__(256)
gemm_tf32(const float* __restrict__ A, const float* __restrict__ W,
          float* __restrict__ out, int M, int K)
{
    constexpr int BM = 128, BK = 16;
    constexpr int LDA = BK + 4;          // bank-conflict-free for A frag pattern
    constexpr int LDB = BN + 8;          // (LDB % 32 == 8) -> conflict-free B frag
    constexpr int NF  = BN / 16;         // n-frags per warp (warp covers BN/2 cols)
    constexpr int F4PR = BN / 4;         // float4s per W row
    constexpr int B_ITERS = (BK * F4PR) / 256;   // 2 for BN=128, 1 for BN=64

    __shared__ unsigned As_hi[BM * LDA], As_lo[BM * LDA];
    __shared__ unsigned Bs_hi[BK * LDB], Bs_lo[BK * LDB];

    const int tid  = threadIdx.x;
    const int lane = tid & 31, warp = tid >> 5;
    const int wm = warp & 3, wn = warp >> 2;   // 4 x 2 warp grid
    const int row0 = blockIdx.x * BM;

    float acc[2][NF][4];
#pragma unroll
    for (int mf = 0; mf < 2; mf++)
#pragma unroll
        for (int nf = 0; nf < NF; nf++)
#pragma unroll
            for (int j = 0; j < 4; j++) acc[mf][nf][j] = 0.0f;

    for (int kk = 0; kk < K; kk += BK) {
        // stage A tile [BM x BK]
#pragma unroll
        for (int i = 0; i < 2; i++) {
            int flat = tid + i * 256;            // 512 float4s
            int r = flat >> 2, c = (flat & 3) * 4;
            float4 v = make_float4(0.f, 0.f, 0.f, 0.f);
            if (row0 + r < M)
                v = *reinterpret_cast<const float4*>(A + (size_t)(row0 + r) * K + kk + c);
            unsigned h, l;
            cvt_split(v.x, h, l); As_hi[r*LDA + c    ] = h; As_lo[r*LDA + c    ] = l;
            cvt_split(v.y, h, l); As_hi[r*LDA + c + 1] = h; As_lo[r*LDA + c + 1] = l;
            cvt_split(v.z, h, l); As_hi[r*LDA + c + 2] = h; As_lo[r*LDA + c + 2] = l;
            cvt_split(v.w, h, l); As_hi[r*LDA + c + 3] = h; As_lo[r*LDA + c + 3] = l;
        }
        // stage W tile [BK x BN]
#pragma unroll
        for (int i = 0; i < B_ITERS; i++) {
            int flat = tid + i * 256;
            int r = flat / F4PR, c = (flat % F4PR) * 4;
            float4 v = *reinterpret_cast<const float4*>(W + (size_t)(kk + r) * BN + c);
            unsigned h, l;
            cvt_split(v.x, h, l); Bs_hi[r*LDB + c    ] = h; Bs_lo[r*LDB + c    ] = l;
            cvt_split(v.y, h, l); Bs_hi[r*LDB + c + 1] = h; Bs_lo[r*LDB + c + 1] = l;
            cvt_split(v.z, h, l); Bs_hi[r*LDB + c + 2] = h; Bs_lo[r*LDB + c + 2] = l;
            cvt_split(v.w, h, l); Bs_hi[r*LDB + c + 3] = h; Bs_lo[r*LDB + c + 3] = l;
        }
        __syncthreads();

#pragma unroll
        for (int ks = 0; ks < 2; ks++) {
            const int k0 = ks * 8;
            unsigned ah[2][4], al[2][4];
#pragma unroll
            for (int mf = 0; mf < 2; mf++) {
                int r = wm * 32 + mf * 16 + (lane >> 2);
                int c = k0 + (lane & 3);
                ah[mf][0] = As_hi[ r      * LDA + c    ];
                ah[mf][1] = As_hi[(r + 8) * LDA + c    ];
                ah[mf][2] = As_hi[ r      * LDA + c + 4];
                ah[mf][3] = As_hi[(r + 8) * LDA + c + 4];
                al[mf][0] = As_lo[ r      * LDA + c    ];
                al[mf][1] = As_lo[(r + 8) * LDA + c    ];
                al[mf][2] = As_lo[ r      * LDA + c + 4];
                al[mf][3] = As_lo[(r + 8) * LDA + c + 4];
            }
#pragma unroll
            for (int nf = 0; nf < NF; nf++) {
                int n = wn * (BN / 2) + nf * 8 + (lane >> 2);
                int kb = k0 + (lane & 3);
                unsigned bh[2], bl[2];
                bh[0] = Bs_hi[ kb      * LDB + n];
                bh[1] = Bs_hi[(kb + 4) * LDB + n];
                bl[0] = Bs_lo[ kb      * LDB + n];
                bl[1] = Bs_lo[(kb + 4) * LDB + n];
#pragma unroll
                for (int mf = 0; mf < 2; mf++) {
                    mma8(acc[mf][nf], ah[mf], bh);   // hi*hi
                    mma8(acc[mf][nf], ah[mf], bl);   // hi*lo
                    mma8(acc[mf][nf], al[mf], bh);   // lo*hi
                }
            }
        }
        __syncthreads();
    }

    // epilogue: scale by dis[row]
#pragma unroll
    for (int mf = 0; mf < 2; mf++) {
        int r0 = row0 + wm * 32 + mf * 16 + (lane >> 2);
        int r1 = r0 + 8;
        float d0 = (r0 < M) ? g_dis[r0] : 0.f;
        float d1 = (r1 < M) ? g_dis[r1] : 0.f;
#pragma unroll
        for (int nf = 0; nf < NF; nf++) {
            int c = wn * (BN / 2) + nf * 8 + (lane & 3) * 2;
            if (r0 < M) {
                out[(size_t)r0 * BN + c    ] = acc[mf][nf][0] * d0;
                out[(size_t)r0 * BN + c + 1] = acc[mf][nf][1] * d0;
            }
            if (r1 < M) {
                out[(size_t)r1 * BN + c    ] = acc[mf][nf][2] * d1;
                out[(size_t)r1 * BN + c + 1] = acc[mf][nf][3] * d1;
            }
        }
    }
}

// ---------------- gather aggregation, fused epilogue ----------------
__device__ __forceinline__ void acc4(float4& a, const float4 v) {
    a.x += v.x; a.y += v.y; a.z += v.z; a.w += v.w;
}

// F=128: one warp per node, lane handles float4 (32*4 = 128).
__global__ void k_agg128(const float* __restrict__ hs, float* __restrict__ out,
                         const float* __restrict__ bias, int N)
{
    int w = (blockIdx.x * blockDim.x + threadIdx.x) >> 5;
    if (w >= N) return;
    int lane = threadIdx.x & 31;
    const float4* base = (const float4*)hs;

    int beg = g_start[w], cnt = g_cnt[w];
    float4 a0 = base[(size_t)w * 32 + lane];   // self loop term
    float4 a1 = make_float4(0.f, 0.f, 0.f, 0.f);
    int e = 0;
    for (; e + 8 <= cnt; e += 8) {
        int s0 = g_csr[beg+e  ], s1 = g_csr[beg+e+1], s2 = g_csr[beg+e+2], s3 = g_csr[beg+e+3];
        int s4 = g_csr[beg+e+4], s5 = g_csr[beg+e+5], s6 = g_csr[beg+e+6], s7 = g_csr[beg+e+7];
        acc4(a0, base[(size_t)s0*32+lane]); acc4(a1, base[(size_t)s1*32+lane]);
        acc4(a0, base[(size_t)s2*32+lane]); acc4(a1, base[(size_t)s3*32+lane]);
        acc4(a0, base[(size_t)s4*32+lane]); acc4(a1, base[(size_t)s5*32+lane]);
        acc4(a0, base[(size_t)s6*32+lane]); acc4(a1, base[(size_t)s7*32+lane]);
    }
    for (; e + 2 <= cnt; e += 2) {
        int s0 = g_csr[beg+e], s1 = g_csr[beg+e+1];
        acc4(a0, base[(size_t)s0*32+lane]); acc4(a1, base[(size_t)s1*32+lane]);
    }
    if (e < cnt) acc4(a0, base[(size_t)g_csr[beg+e]*32+lane]);

    float d = g_dis[w];
    float4 b = ((const float4*)bias)[lane];
    float4 r;
    r.x = fmaxf(fmaf(d, a0.x + a1.x, b.x), 0.f);
    r.y = fmaxf(fmaf(d, a0.y + a1.y, b.y), 0.f);
    r.z = fmaxf(fmaf(d, a0.z + a1.z, b.z), 0.f);
    r.w = fmaxf(fmaf(d, a0.w + a1.w, b.w), 0.f);
    ((float4*)out)[(size_t)w * 32 + lane] = r;
}

// F=64: half-warp per node, lane handles float4 (16*4 = 64). No relu, writes d_out.
__global__ void k_agg64(const float* __restrict__ hs, float* __restrict__ out,
                        const float* __restrict__ bias, int N)
{
    int t = blockIdx.x * blockDim.x + threadIdx.x;
    int node = t >> 4;
    if (node >= N) return;
    int l = t & 15;
    const float4* base = (const float4*)hs;

    int beg = g_start[node], cnt = g_cnt[node];
    float4 a0 = base[(size_t)node * 16 + l];   // self loop
    float4 a1 = make_float4(0.f, 0.f, 0.f, 0.f);
    int e = 0;
    for (; e + 8 <= cnt; e += 8) {
        int s0 = g_csr[beg+e  ], s1 = g_csr[beg+e+1], s2 = g_csr[beg+e+2], s3 = g_csr[beg+e+3];
        int s4 = g_csr[beg+e+4], s5 = g_csr[beg+e+5], s6 = g_csr[beg+e+6], s7 = g_csr[beg+e+7];
        acc4(a0, base[(size_t)s0*16+l]); acc4(a1, base[(size_t)s1*16+l]);
        acc4(a0, base[(size_t)s2*16+l]); acc4(a1, base[(size_t)s3*16+l]);
        acc4(a0, base[(size_t)s4*16+l]); acc4(a1, base[(size_t)s5*16+l]);
        acc4(a0, base[(size_t)s6*16+l]); acc4(a1, base[(size_t)s7*16+l]);
    }
    for (; e + 2 <= cnt; e += 2) {
        int s0 = g_csr[beg+e], s1 = g_csr[beg+e+1];
        acc4(a0, base[(size_t)s0*16+l]); acc4(a1, base[(size_t)s1*16+l]);
    }
    if (e < cnt) acc4(a0, base[(size_t)g_csr[beg+e]*16+l]);

    float d = g_dis[node];
    float4 b = ((const float4*)bias)[l];
    float4 r;
    r.x = fmaf(d, a0.x + a1.x, b.x);
    r.y = fmaf(d, a0.y + a1.y, b.y);
    r.z = fmaf(d, a0.z + a1.z, b.z);
    r.w = fmaf(d, a0.w + a1.w, b.w);
    ((float4*)out)[(size_t)node * 16 + l] = r;
}

// ---------------- launch ----------------
extern "C" void kernel_launch(void* const* d_in, const int* in_sizes, int n_in,
                              void* d_out, int out_size)
{
    const float* x   = (const float*)d_in[0];
    const void*  ei  = d_in[1];
    const float* W1  = (const float*)d_in[2];
    const float* b1  = (const float*)d_in[3];
    const float* W2  = (const float*)d_in[4];
    const float* b2  = (const float*)d_in[5];
    float*       out = (float*)d_out;

    const int N = in_sizes[0] / IN_C;   // 50000
    const int E = in_sizes[1] / 2;      // 800000
    const int nscan = (N + SCAN_B - 1) / SCAN_B;

    float *p_hs1, *p_act1, *p_hs2;
    cudaGetSymbolAddress((void**)&p_hs1,  g_hs1);
    cudaGetSymbolAddress((void**)&p_act1, g_act1);
    cudaGetSymbolAddress((void**)&p_hs2,  g_hs2);

    // 0) CSR build + dis
    k_detect<<<1, 256>>>((const long long*)ei);
    k_zero_cnt<<<(N + 255) / 256, 256>>>(N);
    k_convert_hist<<<(E + 255) / 256, 256>>>(ei, E);
    k_scan1<<<nscan, SCAN_B>>>(N);
    k_scan2<<<1, SCAN_B>>>(nscan);
    k_scan3<<<(N + 255) / 256, 256>>>(N);
    k_fill<<<(E + 255) / 256, 256>>>(E);

    // 1) layer 1 GEMM (tensor core, split tf32): hs1 = dis * (x @ W1)
    gemm_tf32<HID><<<(N + 127) / 128, 256>>>(x, W1, p_hs1, N, IN_C);

    // 2) layer 1 gather-aggregate + bias + relu
    k_agg128<<<(N * 32 + 255) / 256, 256>>>(p_hs1, p_act1, b1, N);

    // 3) layer 2 GEMM: hs2 = dis * (act1 @ W2)
    gemm_tf32<OUTC><<<(N + 127) / 128, 256>>>(p_act1, W2, p_hs2, N, HID);

    // 4) layer 2 gather-aggregate + bias -> d_out
    k_agg64<<<(N * 16 + 255) / 256, 256>>>(p_hs2, out, b2, N);
}